// round 8
// baseline (speedup 1.0000x reference)
#include <cuda_runtime.h>
#include <cuda_bf16.h>

#define K_BONES 512
#define K_SPLIT 2
#define K_HALF (K_BONES / K_SPLIT)
#define N_PAIRS_HALF (K_HALF / 2)     // 128 bone-pairs per half
#define MAXN 200192
#define SCALE 28.853900817779268f     // SIGMA * log2(e), SIGMA = 20

typedef unsigned long long u64;

// Bone-PAIR-packed table: per pair (bones 2j, 2j+1), 32 floats (128 B):
//   slots [0..3]  : (m1x_a,m1x_b)(m1y..)(m1z..)(bb..)   m1 = -2*S^2*b, bb = S^2*|b|^2
//   slots [4..15] : 12 row-element pairs (R00..t0, R10..t1, R20..t2)
// Every f32x2 operand is a natural 64-bit lane of this layout.
__device__ float g_bones_f[K_BONES * 16];

// Planar (SoA) partial scratch: plane (j, half) of blend accums + s.
__device__ float g_accp[12 * K_SPLIT * MAXN];
__device__ float g_s[K_SPLIT * MAXN];

// ---------------------------------------------------------------------------
// Prep: Gram-Schmidt 6D->rotmat, write bone-pair-packed table. 1 thread/bone.
// rotcont reshape(3,2) row-major: a1=(p0,p2,p4), a2=(p1,p3,p5);
// rotmat columns (b1,b2,b3) => row i = (b1[i],b2[i],b3[i]).
// ---------------------------------------------------------------------------
__global__ void prep_kernel(const float* __restrict__ bone_locs,
                            const float* __restrict__ bone_transf,
                            const int* __restrict__ tidx_p) {
    int k = blockIdx.x * blockDim.x + threadIdx.x;
    if (k >= K_BONES) return;
    const float* p = bone_transf + ((long long)tidx_p[0] * K_BONES + k) * 9;

    float a1x = p[0], a2x = p[1];
    float a1y = p[2], a2y = p[3];
    float a1z = p[4], a2z = p[5];

    float n1 = sqrtf(a1x * a1x + a1y * a1y + a1z * a1z) + 1e-12f;
    float b1x = a1x / n1, b1y = a1y / n1, b1z = a1z / n1;

    float d = b1x * a2x + b1y * a2y + b1z * a2z;
    float cx = a2x - d * b1x, cy = a2y - d * b1y, cz = a2z - d * b1z;
    float n2 = sqrtf(cx * cx + cy * cy + cz * cz) + 1e-12f;
    float b2x = cx / n2, b2y = cy / n2, b2z = cz / n2;

    float b3x = b1y * b2z - b1z * b2y;
    float b3y = b1z * b2x - b1x * b2z;
    float b3z = b1x * b2y - b1y * b2x;

    float bx = bone_locs[3 * k + 0];
    float by = bone_locs[3 * k + 1];
    float bz = bone_locs[3 * k + 2];
    float S2 = SCALE * SCALE;

    int j = k >> 1, lane = k & 1;
    float* dst = g_bones_f + j * 32;
    dst[0 * 2 + lane] = -2.0f * S2 * bx;
    dst[1 * 2 + lane] = -2.0f * S2 * by;
    dst[2 * 2 + lane] = -2.0f * S2 * bz;
    dst[3 * 2 + lane] = S2 * (bx * bx + by * by + bz * bz);

    float rows[12] = {b1x, b2x, b3x, p[6],
                      b1y, b2y, b3y, p[7],
                      b1z, b2z, b3z, p[8]};
    #pragma unroll
    for (int jj = 0; jj < 12; jj++)
        dst[(4 + jj) * 2 + lane] = rows[jj];
}

// ---- packed f32x2 helpers (sm_100a) ---------------------------------------
__device__ __forceinline__ u64 pk2(float lo, float hi) {
    u64 r;
    asm("mov.b64 %0, {%1, %2};" : "=l"(r) : "f"(lo), "f"(hi));
    return r;
}
__device__ __forceinline__ void upk2(u64 v, float& lo, float& hi) {
    asm("mov.b64 {%0, %1}, %2;" : "=f"(lo), "=f"(hi) : "l"(v));
}
__device__ __forceinline__ u64 addx2(u64 a, u64 b) {
    u64 r;
    asm("add.rn.f32x2 %0, %1, %2;" : "=l"(r) : "l"(a), "l"(b));
    return r;
}
__device__ __forceinline__ u64 fmax2(u64 a, u64 b, u64 c) {
    u64 r;
    asm("fma.rn.f32x2 %0, %1, %2, %3;" : "=l"(r) : "l"(a), "l"(b), "l"(c));
    return r;
}

// weight pair (e_a, e_b) for one point against a bone pair
__device__ __forceinline__ u64 weight_pair(u64 d2pair) {
    float da, db;
    upk2(d2pair, da, db);
    da = fmaxf(da, 0.0f);
    db = fmaxf(db, 0.0f);            // FMNMX: alu pipe
    float ra, rb;
    asm("sqrt.approx.f32 %0, %1;" : "=f"(ra) : "f"(da));
    asm("sqrt.approx.f32 %0, %1;" : "=f"(rb) : "f"(db));
    float ea, eb;
    asm("ex2.approx.f32 %0, %1;" : "=f"(ea) : "f"(-ra));
    asm("ex2.approx.f32 %0, %1;" : "=f"(eb) : "f"(-rb));
    return pk2(ea, eb);
}

// ---------------------------------------------------------------------------
// Partial kernel: blockIdx.y = bone half (128 pairs, 16 KB smem). 128 thr,
// 2 points/thread. ALL packed operands are natural lanes of the pair layout:
// no per-iteration dup MOVs. Accumulators are bone-pair-packed; lanes summed
// once at the end. Norm-expansion distance (matches reference numerics).
// ---------------------------------------------------------------------------
__global__ __launch_bounds__(128, 5)
void skin_partial_kernel(const float* __restrict__ xyz, int n) {
    __shared__ ulonglong2 sb[N_PAIRS_HALF * 8];   // 16 KB
    {
        const ulonglong2* gb =
            (const ulonglong2*)g_bones_f + (size_t)blockIdx.y * (N_PAIRS_HALF * 8);
        for (int i = threadIdx.x; i < N_PAIRS_HALF * 8; i += 128)
            sb[i] = gb[i];
    }
    __syncthreads();

    int base = blockIdx.x * 256;
    int i0 = base + threadIdx.x;
    int i1 = i0 + 128;
    bool v0 = i0 < n, v1 = i1 < n;

    float x0 = 0.f, y0 = 0.f, z0 = 0.f, x1 = 0.f, y1 = 0.f, z1 = 0.f;
    if (v0) { x0 = xyz[3 * i0]; y0 = xyz[3 * i0 + 1]; z0 = xyz[3 * i0 + 2]; }
    if (v1) { x1 = xyz[3 * i1]; y1 = xyz[3 * i1 + 1]; z1 = xyz[3 * i1 + 2]; }

    float S2 = SCALE * SCALE;
    // hoisted dup'd point operands (the ONLY pk2 movs outside MUFU packing)
    u64 xd0 = pk2(x0, x0), yd0 = pk2(y0, y0), zd0 = pk2(z0, z0);
    u64 xd1 = pk2(x1, x1), yd1 = pk2(y1, y1), zd1 = pk2(z1, z1);
    float pp0 = S2 * (x0 * x0 + y0 * y0 + z0 * z0);
    float pp1 = S2 * (x1 * x1 + y1 * y1 + z1 * z1);
    u64 ppd0 = pk2(pp0, pp0), ppd1 = pk2(pp1, pp1);

    u64 s0 = 0, s1 = 0;
    u64 A[12], B[12];     // bone-pair-packed accumulators, point0 / point1
    #pragma unroll
    for (int j = 0; j < 12; j++) { A[j] = 0; B[j] = 0; }

    const ulonglong2* q = sb;
    #pragma unroll 2
    for (int pr = 0; pr < N_PAIRS_HALF; pr++, q += 8) {
        ulonglong2 qa = q[0];   // (m1x pair) | (m1y pair)
        ulonglong2 qb = q[1];   // (m1z pair) | (bb pair)

        // d2 = bb + pp + x*m1x + y*m1y + z*m1z   (packed over the bone pair)
        u64 d2a = fmax2(xd0, qa.x, addx2(qb.y, ppd0));
        d2a = fmax2(yd0, qa.y, d2a);
        d2a = fmax2(zd0, qb.x, d2a);
        u64 d2b = fmax2(xd1, qa.x, addx2(qb.y, ppd1));
        d2b = fmax2(yd1, qa.y, d2b);
        d2b = fmax2(zd1, qb.x, d2b);

        u64 e0 = weight_pair(d2a);
        u64 e1 = weight_pair(d2b);
        s0 = addx2(s0, e0);
        s1 = addx2(s1, e1);

        ulonglong2 r0 = q[2], r1 = q[3], r2 = q[4];
        ulonglong2 r3 = q[5], r4 = q[6], r5 = q[7];
        A[0] = fmax2(e0, r0.x, A[0]);   B[0] = fmax2(e1, r0.x, B[0]);
        A[1] = fmax2(e0, r0.y, A[1]);   B[1] = fmax2(e1, r0.y, B[1]);
        A[2] = fmax2(e0, r1.x, A[2]);   B[2] = fmax2(e1, r1.x, B[2]);
        A[3] = fmax2(e0, r1.y, A[3]);   B[3] = fmax2(e1, r1.y, B[3]);
        A[4] = fmax2(e0, r2.x, A[4]);   B[4] = fmax2(e1, r2.x, B[4]);
        A[5] = fmax2(e0, r2.y, A[5]);   B[5] = fmax2(e1, r2.y, B[5]);
        A[6] = fmax2(e0, r3.x, A[6]);   B[6] = fmax2(e1, r3.x, B[6]);
        A[7] = fmax2(e0, r3.y, A[7]);   B[7] = fmax2(e1, r3.y, B[7]);
        A[8] = fmax2(e0, r4.x, A[8]);   B[8] = fmax2(e1, r4.x, B[8]);
        A[9] = fmax2(e0, r4.y, A[9]);   B[9] = fmax2(e1, r4.y, B[9]);
        A[10] = fmax2(e0, r5.x, A[10]); B[10] = fmax2(e1, r5.x, B[10]);
        A[11] = fmax2(e0, r5.y, A[11]); B[11] = fmax2(e1, r5.y, B[11]);
    }

    size_t hb = (size_t)blockIdx.y * MAXN;
    if (v0) {
        #pragma unroll
        for (int j = 0; j < 12; j++) {
            float lo, hi;  upk2(A[j], lo, hi);
            g_accp[((size_t)j * K_SPLIT + blockIdx.y) * MAXN + i0] = lo + hi;
        }
        float lo, hi;  upk2(s0, lo, hi);
        g_s[hb + i0] = lo + hi;
    }
    if (v1) {
        #pragma unroll
        for (int j = 0; j < 12; j++) {
            float lo, hi;  upk2(B[j], lo, hi);
            g_accp[((size_t)j * K_SPLIT + blockIdx.y) * MAXN + i1] = lo + hi;
        }
        float lo, hi;  upk2(s1, lo, hi);
        g_s[hb + i1] = lo + hi;
    }
}

// ---------------------------------------------------------------------------
// Finalize: merge halves (exact partial-softmax combine), apply, write.
// All loads perfectly coalesced (planar scratch).
// ---------------------------------------------------------------------------
__global__ __launch_bounds__(256)
void finalize_kernel(const float* __restrict__ xyz,
                     float* __restrict__ out, int n) {
    int i = blockIdx.x * blockDim.x + threadIdx.x;
    if (i >= n) return;

    float a[12];
    #pragma unroll
    for (int j = 0; j < 12; j++)
        a[j] = g_accp[((size_t)j * K_SPLIT + 0) * MAXN + i] +
               g_accp[((size_t)j * K_SPLIT + 1) * MAXN + i];
    float s = g_s[i] + g_s[MAXN + i];

    float x = xyz[3 * i], y = xyz[3 * i + 1], z = xyz[3 * i + 2];
    float inv;
    asm("rcp.approx.f32 %0, %1;" : "=f"(inv) : "f"(s));

    out[3 * i + 0] = fmaf(a[0], x, fmaf(a[1], y, fmaf(a[2], z, a[3]))) * inv;
    out[3 * i + 1] = fmaf(a[4], x, fmaf(a[5], y, fmaf(a[6], z, a[7]))) * inv;
    out[3 * i + 2] = fmaf(a[8], x, fmaf(a[9], y, fmaf(a[10], z, a[11]))) * inv;
}

extern "C" void kernel_launch(void* const* d_in, const int* in_sizes, int n_in,
                              void* d_out, int out_size) {
    const float* xyz  = (const float*)d_in[0];   // [N, 3]
    const float* locs = (const float*)d_in[1];   // [512, 3]
    const float* bt   = (const float*)d_in[2];   // [64, 512, 9]
    const int*   tidx = (const int*)d_in[3];     // scalar

    int n = in_sizes[0] / 3;

    prep_kernel<<<4, 128>>>(locs, bt, tidx);

    dim3 grid((n + 255) / 256, K_SPLIT);
    skin_partial_kernel<<<grid, 128>>>(xyz, n);

    finalize_kernel<<<(n + 255) / 256, 256>>>(xyz, (float*)d_out, n);
}

// round 9
// speedup vs baseline: 1.0692x; 1.0692x over previous
#include <cuda_runtime.h>
#include <cuda_bf16.h>

#define K_BONES 512
#define K_SPLIT 2
#define K_HALF (K_BONES / K_SPLIT)
#define N_PAIRS_HALF (K_HALF / 2)     // 128 bone-pairs per half
#define MAXN 200192
#define SCALE 28.853900817779268f     // SIGMA * log2(e), SIGMA = 20

typedef unsigned long long u64;

// Partial per (half, point): float4 (ox, oy, oz, s). Planar, coalesced.
__device__ float4 g_part[K_SPLIT * MAXN];

// ---- packed f32x2 helpers (sm_100a) ---------------------------------------
__device__ __forceinline__ u64 pk2(float lo, float hi) {
    u64 r;
    asm("mov.b64 %0, {%1, %2};" : "=l"(r) : "f"(lo), "f"(hi));
    return r;
}
__device__ __forceinline__ void upk2(u64 v, float& lo, float& hi) {
    asm("mov.b64 {%0, %1}, %2;" : "=f"(lo), "=f"(hi) : "l"(v));
}
__device__ __forceinline__ u64 addx2(u64 a, u64 b) {
    u64 r;
    asm("add.rn.f32x2 %0, %1, %2;" : "=l"(r) : "l"(a), "l"(b));
    return r;
}
__device__ __forceinline__ u64 fmax2(u64 a, u64 b, u64 c) {
    u64 r;
    asm("fma.rn.f32x2 %0, %1, %2, %3;" : "=l"(r) : "l"(a), "l"(b), "l"(c));
    return r;
}

// weight pair (e_a, e_b) for one point vs a bone pair: e = ex2(-sqrt(max(d2,0)))
__device__ __forceinline__ u64 weight_pair(u64 d2pair) {
    float da, db;
    upk2(d2pair, da, db);
    da = fmaxf(da, 0.0f);            // FMNMX: alu pipe
    db = fmaxf(db, 0.0f);
    float ra, rb;
    asm("sqrt.approx.f32 %0, %1;" : "=f"(ra) : "f"(da));
    asm("sqrt.approx.f32 %0, %1;" : "=f"(rb) : "f"(db));
    float ea, eb;
    asm("ex2.approx.f32 %0, %1;" : "=f"(ea) : "f"(-ra));
    asm("ex2.approx.f32 %0, %1;" : "=f"(eb) : "f"(-rb));
    return pk2(ea, eb);
}

// ---------------------------------------------------------------------------
// Partial kernel, TRANSFORM-FIRST: out_partial = sum_k e_k * (R_k p + t_k),
// s_partial = sum_k e_k. Only 4 packed accumulators per point (was 12+1).
// Bone data pair-packed in smem (every f32x2 operand = natural LDS lane).
// Inline per-block Gram-Schmidt prep (no serialized prep launch).
// blockIdx.y = bone half (128 pairs, 16 KB). 128 thr, 2 points/thread.
// ---------------------------------------------------------------------------
__global__ __launch_bounds__(128, 8)
void skin_partial_kernel(const float* __restrict__ xyz,
                         const float* __restrict__ bone_locs,
                         const float* __restrict__ bone_transf,
                         const int* __restrict__ tidx_p, int n) {
    // Pair-packed bone table: per pair j, 32 floats (16 u64):
    //  u64[0..3] = (m1x|m1y|m1z|bb) pairs, m1 = -2*S^2*b, bb = S^2*|b|^2
    //  u64[4..15] = row-element pairs (R00,R01,R02,t0, R10..t1, R20..t2)
    __shared__ float sbf[K_HALF * 16];   // 16 KB
    {
        int t = tidx_p[0];
        float S2 = SCALE * SCALE;
        for (int kk = threadIdx.x; kk < K_HALF; kk += 128) {
            int k = blockIdx.y * K_HALF + kk;
            const float* p = bone_transf + ((long long)t * K_BONES + k) * 9;

            float a1x = p[0], a2x = p[1];
            float a1y = p[2], a2y = p[3];
            float a1z = p[4], a2z = p[5];

            float n1 = sqrtf(a1x * a1x + a1y * a1y + a1z * a1z) + 1e-12f;
            float b1x = a1x / n1, b1y = a1y / n1, b1z = a1z / n1;

            float d = b1x * a2x + b1y * a2y + b1z * a2z;
            float cx = a2x - d * b1x, cy = a2y - d * b1y, cz = a2z - d * b1z;
            float n2 = sqrtf(cx * cx + cy * cy + cz * cz) + 1e-12f;
            float b2x = cx / n2, b2y = cy / n2, b2z = cz / n2;

            float b3x = b1y * b2z - b1z * b2y;
            float b3y = b1z * b2x - b1x * b2z;
            float b3z = b1x * b2y - b1y * b2x;

            float bx = bone_locs[3 * k + 0];
            float by = bone_locs[3 * k + 1];
            float bz = bone_locs[3 * k + 2];

            int j = kk >> 1, lane = kk & 1;
            float* dst = sbf + j * 32;
            dst[0 * 2 + lane] = -2.0f * S2 * bx;
            dst[1 * 2 + lane] = -2.0f * S2 * by;
            dst[2 * 2 + lane] = -2.0f * S2 * bz;
            dst[3 * 2 + lane] = S2 * (bx * bx + by * by + bz * bz);
            float rows[12] = {b1x, b2x, b3x, p[6],
                              b1y, b2y, b3y, p[7],
                              b1z, b2z, b3z, p[8]};
            #pragma unroll
            for (int r = 0; r < 12; r++)
                dst[(4 + r) * 2 + lane] = rows[r];
        }
    }
    __syncthreads();

    int base = blockIdx.x * 256;
    int i0 = base + threadIdx.x;
    int i1 = i0 + 128;
    bool v0 = i0 < n, v1 = i1 < n;

    float x0 = 0.f, y0 = 0.f, z0 = 0.f, x1 = 0.f, y1 = 0.f, z1 = 0.f;
    if (v0) { x0 = xyz[3 * i0]; y0 = xyz[3 * i0 + 1]; z0 = xyz[3 * i0 + 2]; }
    if (v1) { x1 = xyz[3 * i1]; y1 = xyz[3 * i1 + 1]; z1 = xyz[3 * i1 + 2]; }

    float S2 = SCALE * SCALE;
    // hoisted loop-invariant dup operands
    u64 xd0 = pk2(x0, x0), yd0 = pk2(y0, y0), zd0 = pk2(z0, z0);
    u64 xd1 = pk2(x1, x1), yd1 = pk2(y1, y1), zd1 = pk2(z1, z1);
    float pp0 = S2 * (x0 * x0 + y0 * y0 + z0 * z0);
    float pp1 = S2 * (x1 * x1 + y1 * y1 + z1 * z1);
    u64 ppd0 = pk2(pp0, pp0), ppd1 = pk2(pp1, pp1);

    // 4 packed accumulators per point (lanes = bone-pair halves)
    u64 ox0 = 0, oy0 = 0, oz0 = 0, s0 = 0;
    u64 ox1 = 0, oy1 = 0, oz1 = 0, s1 = 0;

    const ulonglong2* q = (const ulonglong2*)sbf;
    #pragma unroll 2
    for (int pr = 0; pr < N_PAIRS_HALF; pr++, q += 8) {
        ulonglong2 qm0 = q[0];   // m1x | m1y
        ulonglong2 qm1 = q[1];   // m1z | bb

        // d2 = bb + pp + x*m1x + y*m1y + z*m1z  (packed over the bone pair)
        u64 d2a = fmax2(xd0, qm0.x, addx2(qm1.y, ppd0));
        d2a = fmax2(yd0, qm0.y, d2a);
        d2a = fmax2(zd0, qm1.x, d2a);
        u64 d2b = fmax2(xd1, qm0.x, addx2(qm1.y, ppd1));
        d2b = fmax2(yd1, qm0.y, d2b);
        d2b = fmax2(zd1, qm1.x, d2b);

        u64 e0 = weight_pair(d2a);
        u64 e1 = weight_pair(d2b);
        s0 = addx2(s0, e0);
        s1 = addx2(s1, e1);

        ulonglong2 r0 = q[2];    // R00 | R01
        ulonglong2 r1 = q[3];    // R02 | t0
        ulonglong2 r2 = q[4];    // R10 | R11
        ulonglong2 r3 = q[5];    // R12 | t1
        ulonglong2 r4 = q[6];    // R20 | R21
        ulonglong2 r5 = q[7];    // R22 | t2

        // y_row = R p + t (packed over bone pair), then o += e * y_row
        u64 h;
        h = fmax2(xd0, r0.x, r1.y); h = fmax2(yd0, r0.y, h);
        h = fmax2(zd0, r1.x, h);    ox0 = fmax2(e0, h, ox0);
        h = fmax2(xd0, r2.x, r3.y); h = fmax2(yd0, r2.y, h);
        h = fmax2(zd0, r3.x, h);    oy0 = fmax2(e0, h, oy0);
        h = fmax2(xd0, r4.x, r5.y); h = fmax2(yd0, r4.y, h);
        h = fmax2(zd0, r5.x, h);    oz0 = fmax2(e0, h, oz0);

        h = fmax2(xd1, r0.x, r1.y); h = fmax2(yd1, r0.y, h);
        h = fmax2(zd1, r1.x, h);    ox1 = fmax2(e1, h, ox1);
        h = fmax2(xd1, r2.x, r3.y); h = fmax2(yd1, r2.y, h);
        h = fmax2(zd1, r3.x, h);    oy1 = fmax2(e1, h, oy1);
        h = fmax2(xd1, r4.x, r5.y); h = fmax2(yd1, r4.y, h);
        h = fmax2(zd1, r5.x, h);    oz1 = fmax2(e1, h, oz1);
    }

    size_t hb = (size_t)blockIdx.y * MAXN;
    if (v0) {
        float a, b, ox, oy, oz, s;
        upk2(ox0, a, b); ox = a + b;
        upk2(oy0, a, b); oy = a + b;
        upk2(oz0, a, b); oz = a + b;
        upk2(s0, a, b);  s  = a + b;
        g_part[hb + i0] = make_float4(ox, oy, oz, s);
    }
    if (v1) {
        float a, b, ox, oy, oz, s;
        upk2(ox1, a, b); ox = a + b;
        upk2(oy1, a, b); oy = a + b;
        upk2(oz1, a, b); oz = a + b;
        upk2(s1, a, b);  s  = a + b;
        g_part[hb + i1] = make_float4(ox, oy, oz, s);
    }
}

// ---------------------------------------------------------------------------
// Finalize: merge the two halves (exact partial-softmax combine) and divide.
// ~6.4 MB read + 2.4 MB write, fully coalesced float4.
// ---------------------------------------------------------------------------
__global__ __launch_bounds__(256)
void finalize_kernel(float* __restrict__ out, int n) {
    int i = blockIdx.x * blockDim.x + threadIdx.x;
    if (i >= n) return;

    float4 p0 = g_part[i];
    float4 p1 = g_part[MAXN + i];
    float inv;
    asm("rcp.approx.f32 %0, %1;" : "=f"(inv) : "f"(p0.w + p1.w));

    out[3 * i + 0] = (p0.x + p1.x) * inv;
    out[3 * i + 1] = (p0.y + p1.y) * inv;
    out[3 * i + 2] = (p0.z + p1.z) * inv;
}

extern "C" void kernel_launch(void* const* d_in, const int* in_sizes, int n_in,
                              void* d_out, int out_size) {
    const float* xyz  = (const float*)d_in[0];   // [N, 3]
    const float* locs = (const float*)d_in[1];   // [512, 3]
    const float* bt   = (const float*)d_in[2];   // [64, 512, 9]
    const int*   tidx = (const int*)d_in[3];     // scalar

    int n = in_sizes[0] / 3;

    dim3 grid((n + 255) / 256, K_SPLIT);
    skin_partial_kernel<<<grid, 128>>>(xyz, locs, bt, tidx, n);

    finalize_kernel<<<(n + 255) / 256, 256>>>((float*)d_out, n);
}